// round 16
// baseline (speedup 1.0000x reference)
#include <cuda_runtime.h>
#include <math.h>

#define BD 8
#define HD 48
#define WD 48
#define CD 256
#define NPIX (BD * HD * WD)     // 18432
#define PIXB (HD * WD)          // 2304 pixels per batch
#define PLANE (HD * WD)         // 2304 elems per corr plane
#define PPB   16                // pixels per k_stats block (8 warps x 2)
#define NBLK1 (NPIX / PPB)      // 1152
#define BLKPB (PIXB / PPB)      // 144 stats blocks per batch

// ---- scratch (device globals; no allocation allowed) ----
__device__ float g_cvraw[NPIX * 2];
__device__ float g_partials[NBLK1 * 2];   // (sum, sumsq) per block
__device__ float g_stats[BD * 2];         // (mu, inv_std) per batch

// ================= Kernel 1: MLP + mean output + cv raw + block partials ============
// Lane (slot, o): lanes 0-15 -> outputs 0-15 of pixel A, lanes 16-31 -> pixel B.
// Each lane owns the FULL 256-channel dot: 256 FFMA + 64 LDS + 64 LDG per warp,
// ZERO shuffles, no register arrays. Weights transposed in smem (wT4[ch4][o]:
// 16 consecutive float4 per access = conflict-free; halves broadcast-share).
// x read straight from GMEM: half-warp same-address float4 loads (2 lines/warp).
__global__ __launch_bounds__(256) void k_stats(
    const float* __restrict__ x,
    const float* __restrict__ map_w, const float* __restrict__ map_b,
    const float* __restrict__ mean_w, const float* __restrict__ mean_b,
    const float* __restrict__ cov_w, const float* __restrict__ cov_b,
    float* __restrict__ out_mean)
{
    __shared__ float4 wT4[64 * 16];       // 16KB transposed weights [ch4][o]
    __shared__ float tts[PPB * 17];       // tanh outputs, stride 17 (conflict-free)
    __shared__ float sS[PPB], sQ[PPB];    // per-pixel cv sums
    const int tid = threadIdx.x;

    {   // transposed weight stage (one-time; weights L2-hot across blocks)
        const float4* w4 = (const float4*)map_w;   // [o][ch4]
        for (int i = tid; i < 1024; i += 256) {
            const int o = i & 15, ch4 = i >> 4;
            wT4[ch4 * 16 + o] = w4[o * 64 + ch4];
        }
    }
    __syncthreads();

    const int warp = tid >> 5, lane = tid & 31;
    const int o = lane & 15, slot = lane >> 4;
    const int lpx = warp * 2 + slot;                 // local pixel 0..15
    const int pid = blockIdx.x * PPB + lpx;
    const float4* __restrict__ xp = (const float4*)x + (size_t)pid * 64;

    // full 256-ch dot per lane; dual accumulators for FMA ILP
    float acc0 = 0.f, acc1 = 0.f;
#pragma unroll
    for (int ch4 = 0; ch4 < 64; ch4 += 2) {
        const float4 xa = __ldg(xp + ch4);
        const float4 xb = __ldg(xp + ch4 + 1);
        const float4 wa = wT4[ch4 * 16 + o];
        const float4 wb = wT4[(ch4 + 1) * 16 + o];
        acc0 = fmaf(xa.x, wa.x, acc0); acc0 = fmaf(xa.y, wa.y, acc0);
        acc0 = fmaf(xa.z, wa.z, acc0); acc0 = fmaf(xa.w, wa.w, acc0);
        acc1 = fmaf(xb.x, wb.x, acc1); acc1 = fmaf(xb.y, wb.y, acc1);
        acc1 = fmaf(xb.z, wb.z, acc1); acc1 = fmaf(xb.w, wb.w, acc1);
    }
    const float tt = tanhf(acc0 + acc1 + __ldg(&map_b[o]));
    tts[lpx * 17 + o] = tt;
    __syncthreads();

    // Head MLP: thread t (<16) handles local pixel t (stride-17: conflict-free)
    if (tid < PPB) {
        const int mypid = blockIdx.x * PPB + tid;
        float m0 = __ldg(&mean_b[0]), m1 = __ldg(&mean_b[1]);
        float c0 = __ldg(&cov_b[0]),  c1 = __ldg(&cov_b[1]);
        const float* tp = tts + tid * 17;
#pragma unroll
        for (int k = 0; k < 16; k++) {
            const float t = tp[k];
            m0 = fmaf(t, __ldg(&mean_w[k]),      m0);
            m1 = fmaf(t, __ldg(&mean_w[16 + k]), m1);
            c0 = fmaf(t, __ldg(&cov_w[k]),       c0);
            c1 = fmaf(t, __ldg(&cov_w[16 + k]),  c1);
        }
        const int hw = mypid % PIXB;
        out_mean[mypid * 2 + 0] = (float)(hw % WD) + m0;
        out_mean[mypid * 2 + 1] = (float)(hw / WD) + m1;
        g_cvraw[mypid * 2 + 0] = c0;
        g_cvraw[mypid * 2 + 1] = c1;
        sS[tid] = c0 + c1;
        sQ[tid] = c0 * c0 + c1 * c1;
    }
    __syncthreads();

    // deterministic fixed-order block partial (block never straddles batch)
    if (tid == 0) {
        float s = 0.f, q = 0.f;
#pragma unroll
        for (int i = 0; i < PPB; i++) { s += sS[i]; q += sQ[i]; }
        g_partials[blockIdx.x * 2 + 0] = s;
        g_partials[blockIdx.x * 2 + 1] = q;
    }
}

// ================= Kernel 2: per-batch reduction (deterministic tree) =================
__global__ __launch_bounds__(256) void k_reduce()
{
    __shared__ float s[256], q[256];
    const int b = blockIdx.x, t = threadIdx.x;
    float sv = 0.f, qv = 0.f;
    if (t < BLKPB) {
        sv = g_partials[(b * BLKPB + t) * 2 + 0];
        qv = g_partials[(b * BLKPB + t) * 2 + 1];
    }
    s[t] = sv; q[t] = qv;
    __syncthreads();
    for (int off = 128; off; off >>= 1) {
        if (t < off) { s[t] += s[t + off]; q[t] += q[t + off]; }
        __syncthreads();
    }
    if (t == 0) {
        const float n = (float)(PIXB * 2);     // 4608
        const float mu = s[0] / n;
        const float var = q[0] / n - mu * mu + 1e-5f;
        g_stats[b * 2 + 0] = mu;
        g_stats[b * 2 + 1] = rsqrtf(var);
    }
}

// ================= Kernel 3: HBM-bound apply (best measured: 47.1us, 76.5% DRAM) ===
__global__ __launch_bounds__(192) void k_apply(
    const float* __restrict__ corr, float* __restrict__ out,
    const float* __restrict__ mean_arr, float* __restrict__ out_det)
{
    const int pid = blockIdx.x;
    const int t = threadIdx.x;
    const float4* __restrict__ src = (const float4*)(corr + (size_t)pid * PLANE);
    float4* __restrict__ dst = (float4*)(out + (size_t)pid * PLANE);

    // issue the 3 streaming DRAM loads first (MLP=3), overlap with param math
    float4 c[3];
#pragma unroll
    for (int it = 0; it < 3; it++) c[it] = __ldcs(src + t + it * 192);

    // per-pixel params (redundant per thread; same-address broadcast, L2-hit)
    const int b = pid / PIXB;
    const float mu = g_stats[b * 2 + 0], istd = g_stats[b * 2 + 1];
    float c0 = (g_cvraw[pid * 2 + 0] - mu) * istd;
    float c1 = (g_cvraw[pid * 2 + 1] - mu) * istd;
    c0 = 5.f / (1.f + __expf(-c0)) + 0.05f;
    c1 = 5.f / (1.f + __expf(-c1)) + 0.05f;
    const float det = c0 * c1;
    if (t == 0) out_det[pid] = det;
    const float mx = __ldg(&mean_arr[pid * 2 + 0]);
    const float my = __ldg(&mean_arr[pid * 2 + 1]);
    const float ax = -0.5f / c0;
    const float ay = -0.5f / c1;
    const float s = rsqrtf(det) * (1.0f / 6.28f);

#pragma unroll
    for (int it = 0; it < 3; it++) {
        const int i = t + it * 192;          // float4 index in plane (0..575)
        const int h2 = i / 12;               // 12 float4s per 48-float row
        const float dy = (float)h2 - my;
        const bool iny = fabsf(dy) <= 6.0f;
        const float qy = ay * dy * dy;
        const float dx0 = (float)((i % 12) * 4) - mx;
        float4 v = c[it];
        {
            const float dx = dx0 + 0.f;
            if (iny && fabsf(dx) <= 6.0f)
                v.x = fmaf(v.x * s, __expf(fmaf(ax, dx * dx, qy)), v.x);
        }
        {
            const float dx = dx0 + 1.f;
            if (iny && fabsf(dx) <= 6.0f)
                v.y = fmaf(v.y * s, __expf(fmaf(ax, dx * dx, qy)), v.y);
        }
        {
            const float dx = dx0 + 2.f;
            if (iny && fabsf(dx) <= 6.0f)
                v.z = fmaf(v.z * s, __expf(fmaf(ax, dx * dx, qy)), v.z);
        }
        {
            const float dx = dx0 + 3.f;
            if (iny && fabsf(dx) <= 6.0f)
                v.w = fmaf(v.w * s, __expf(fmaf(ax, dx * dx, qy)), v.w);
        }
        __stcs(dst + i, v);
    }
}

// ======================================================================
extern "C" void kernel_launch(void* const* d_in, const int* in_sizes, int n_in,
                              void* d_out, int out_size)
{
    const float* x      = (const float*)d_in[0];
    const float* corr   = (const float*)d_in[1];
    const float* map_w  = (const float*)d_in[2];
    const float* map_b  = (const float*)d_in[3];
    const float* mean_w = (const float*)d_in[4];
    const float* mean_b = (const float*)d_in[5];
    const float* cov_w  = (const float*)d_in[6];
    const float* cov_b  = (const float*)d_in[7];

    float* out = (float*)d_out;
    // outputs concatenated flat: corr1 (b,h,w,h,w), mean (b,h,w,2), det (b,h*w)
    float* out_corr1 = out;
    float* out_mean  = out + (size_t)NPIX * PLANE;
    float* out_det   = out_mean + (size_t)NPIX * 2;

    k_stats<<<NBLK1, 256>>>(x, map_w, map_b, mean_w, mean_b, cov_w, cov_b, out_mean);
    k_reduce<<<BD, 256>>>();
    k_apply<<<NPIX, 192>>>(corr, out_corr1, out_mean, out_det);
}

// round 17
// speedup vs baseline: 1.3657x; 1.3657x over previous
#include <cuda_runtime.h>
#include <math.h>

#define BD 8
#define HD 48
#define WD 48
#define CD 256
#define NPIX (BD * HD * WD)     // 18432
#define PIXB (HD * WD)          // 2304 pixels per batch
#define PLANE (HD * WD)         // 2304 elems per corr plane
#define PPB   16                // pixels per k_stats block (8 warps x 2)
#define NBLK1 (NPIX / PPB)      // 1152
#define BLKPB (PIXB / PPB)      // 144 stats blocks per batch

// ---- scratch (device globals; no allocation allowed) ----
__device__ float g_cvraw[NPIX * 2];
__device__ float g_partials[NBLK1 * 2];   // (sum, sumsq) per block

// ================= Kernel 1: MLP + mean output + cv raw + block partials ============
// Byte-exact R8 body (measured 15.0us): x in registers, conflict-free lane-indexed
// weight LDS, multi-value butterfly. Writes per-block partials only.
__global__ __launch_bounds__(256) void k_stats(
    const float* __restrict__ x,
    const float* __restrict__ map_w, const float* __restrict__ map_b,
    const float* __restrict__ mean_w, const float* __restrict__ mean_b,
    const float* __restrict__ cov_w, const float* __restrict__ cov_b,
    float* __restrict__ out_mean)
{
    __shared__ float4 sw4[16 * 64];   // map_w as float4 [o][c/4], 16KB
    __shared__ float red[PPB * 2];    // per-pixel (sum, sumsq)
    const int tid = threadIdx.x;
    {
        const float4* w4 = (const float4*)map_w;
        for (int i = tid; i < 16 * 64; i += 256) sw4[i] = w4[i];
    }
    __syncthreads();

    const int warp = tid >> 5, lane = tid & 31;
    const int pidA = blockIdx.x * PPB + warp * 2;   // pixel A (B = A+1)

    const float4* __restrict__ x4 = (const float4*)x;
    const float4 xA0 = x4[(size_t)pidA * 64 + lane];
    const float4 xA1 = x4[(size_t)pidA * 64 + 32 + lane];
    const float4 xB0 = x4[(size_t)(pidA + 1) * 64 + lane];
    const float4 xB1 = x4[(size_t)(pidA + 1) * 64 + 32 + lane];

    float acc[32];
#pragma unroll
    for (int o = 0; o < 16; o++) {
        const float4 w0 = sw4[o * 64 + lane];
        const float4 w1 = sw4[o * 64 + 32 + lane];
        float a = xA0.x * w0.x;
        a = fmaf(xA0.y, w0.y, a); a = fmaf(xA0.z, w0.z, a); a = fmaf(xA0.w, w0.w, a);
        a = fmaf(xA1.x, w1.x, a); a = fmaf(xA1.y, w1.y, a);
        a = fmaf(xA1.z, w1.z, a); a = fmaf(xA1.w, w1.w, a);
        float c = xB0.x * w0.x;
        c = fmaf(xB0.y, w0.y, c); c = fmaf(xB0.z, w0.z, c); c = fmaf(xB0.w, w0.w, c);
        c = fmaf(xB1.x, w1.x, c); c = fmaf(xB1.y, w1.y, c);
        c = fmaf(xB1.z, w1.z, c); c = fmaf(xB1.w, w1.w, c);
        acc[o] = a;
        acc[16 + o] = c;
    }

    // Multi-value butterfly: lane l ends holding the full sum of acc[l]
#pragma unroll
    for (int d = 16; d >= 1; d >>= 1) {
        const int half = d;
#pragma unroll
        for (int j = 0; j < 16; j++) {
            if (j < half) {
                float send = (lane & d) ? acc[j] : acc[j + half];
                float recv = __shfl_xor_sync(0xffffffffu, send, d);
                float mine = (lane & d) ? acc[j + half] : acc[j];
                acc[j] = mine + recv;
            }
        }
    }
    const int o = lane & 15;
    const float tt = tanhf(acc[0] + __ldg(&map_b[o]));

    float vals[4];
    vals[0] = tt * __ldg(&mean_w[o]);
    vals[1] = tt * __ldg(&mean_w[16 + o]);
    vals[2] = tt * __ldg(&cov_w[o]);
    vals[3] = tt * __ldg(&cov_w[16 + o]);
    {   // d=8: 4->2
        float send = (lane & 8) ? vals[0] : vals[2];
        float recv = __shfl_xor_sync(0xffffffffu, send, 8);
        vals[0] = ((lane & 8) ? vals[2] : vals[0]) + recv;
        send = (lane & 8) ? vals[1] : vals[3];
        recv = __shfl_xor_sync(0xffffffffu, send, 8);
        vals[1] = ((lane & 8) ? vals[3] : vals[1]) + recv;
    }
    {   // d=4: 2->1
        float send = (lane & 4) ? vals[0] : vals[1];
        float recv = __shfl_xor_sync(0xffffffffu, send, 4);
        vals[0] = ((lane & 4) ? vals[1] : vals[0]) + recv;
    }
    vals[0] += __shfl_xor_sync(0xffffffffu, vals[0], 2);
    vals[0] += __shfl_xor_sync(0xffffffffu, vals[0], 1);
    // quad q = (lane&15)>>2: q0=m0, q1=m1, q2=c0, q3=c1 (replicated x4)

    const int p = lane >> 4;
    const int pid = pidA + p;
    const int hl = lane & 15;
    const int q = hl >> 2;
    const int hw = pid % PIXB;
    const float r = vals[0];

    if (hl == 0) out_mean[pid * 2 + 0] = (float)(hw % WD) + __ldg(&mean_b[0]) + r;
    if (hl == 4) out_mean[pid * 2 + 1] = (float)(hw / WD) + __ldg(&mean_b[1]) + r;

    const float cb = r + __ldg(&cov_b[q & 1]);
    const float ex = __shfl_xor_sync(0xffffffffu, cb, 4);
    if (hl == 8)  g_cvraw[pid * 2 + 0] = cb;
    if (hl == 12) g_cvraw[pid * 2 + 1] = cb;
    if (hl == 8) {
        red[(warp * 2 + p) * 2 + 0] = cb + ex;
        red[(warp * 2 + p) * 2 + 1] = cb * cb + ex * ex;
    }
    __syncthreads();

    // deterministic fixed-order block partial (block never straddles batch)
    if (tid == 0) {
        float s = 0.f, qq = 0.f;
#pragma unroll
        for (int i = 0; i < PPB; i++) { s += red[i * 2]; qq += red[i * 2 + 1]; }
        g_partials[blockIdx.x * 2 + 0] = s;
        g_partials[blockIdx.x * 2 + 1] = qq;
    }
}

// ================= Kernel 2: HBM-bound apply + inline deterministic reduce ==========
// Each block redundantly reduces its batch's 144 partials (identical fixed-order
// smem tree in every block -> bitwise-deterministic), fully under the shadow of
// the 3 already-issued streaming DRAM loads.
__global__ __launch_bounds__(192) void k_apply(
    const float* __restrict__ corr, float* __restrict__ out,
    const float* __restrict__ mean_arr, float* __restrict__ out_det)
{
    __shared__ float ss[256], sq[256];
    const int pid = blockIdx.x;
    const int t = threadIdx.x;
    const float4* __restrict__ src = (const float4*)(corr + (size_t)pid * PLANE);
    float4* __restrict__ dst = (float4*)(out + (size_t)pid * PLANE);

    // issue the 3 streaming DRAM loads first — everything below hides under them
    float4 c[3];
#pragma unroll
    for (int it = 0; it < 3; it++) c[it] = __ldcs(src + t + it * 192);

    // inline per-batch reduction (identical order to the old k_reduce kernel)
    const int b = pid / PIXB;
    {
        float sv = 0.f, qv = 0.f;
        if (t < BLKPB) {
            sv = g_partials[(b * BLKPB + t) * 2 + 0];
            qv = g_partials[(b * BLKPB + t) * 2 + 1];
        }
        ss[t] = sv; sq[t] = qv;
        if (t < 64) { ss[192 + t] = 0.f; sq[192 + t] = 0.f; }
        __syncthreads();
#pragma unroll
        for (int off = 128; off; off >>= 1) {
            if (t < off) { ss[t] += ss[t + off]; sq[t] += sq[t + off]; }
            __syncthreads();
        }
    }
    const float n = (float)(PIXB * 2);          // 4608
    const float mu = ss[0] / n;
    const float var = sq[0] / n - mu * mu + 1e-5f;
    const float istd = rsqrtf(var);

    // per-pixel params (broadcast loads, L2-hit)
    float c0 = (g_cvraw[pid * 2 + 0] - mu) * istd;
    float c1 = (g_cvraw[pid * 2 + 1] - mu) * istd;
    c0 = 5.f / (1.f + __expf(-c0)) + 0.05f;
    c1 = 5.f / (1.f + __expf(-c1)) + 0.05f;
    const float det = c0 * c1;
    if (t == 0) out_det[pid] = det;
    const float mx = __ldg(&mean_arr[pid * 2 + 0]);
    const float my = __ldg(&mean_arr[pid * 2 + 1]);
    const float ax = -0.5f / c0;
    const float ay = -0.5f / c1;
    const float s = rsqrtf(det) * (1.0f / 6.28f);

#pragma unroll
    for (int it = 0; it < 3; it++) {
        const int i = t + it * 192;          // float4 index in plane (0..575)
        const int h2 = i / 12;               // 12 float4s per 48-float row
        const float dy = (float)h2 - my;
        const bool iny = fabsf(dy) <= 6.0f;
        const float qy = ay * dy * dy;
        const float dx0 = (float)((i % 12) * 4) - mx;
        float4 v = c[it];
        {
            const float dx = dx0 + 0.f;
            if (iny && fabsf(dx) <= 6.0f)
                v.x = fmaf(v.x * s, __expf(fmaf(ax, dx * dx, qy)), v.x);
        }
        {
            const float dx = dx0 + 1.f;
            if (iny && fabsf(dx) <= 6.0f)
                v.y = fmaf(v.y * s, __expf(fmaf(ax, dx * dx, qy)), v.y);
        }
        {
            const float dx = dx0 + 2.f;
            if (iny && fabsf(dx) <= 6.0f)
                v.z = fmaf(v.z * s, __expf(fmaf(ax, dx * dx, qy)), v.z);
        }
        {
            const float dx = dx0 + 3.f;
            if (iny && fabsf(dx) <= 6.0f)
                v.w = fmaf(v.w * s, __expf(fmaf(ax, dx * dx, qy)), v.w);
        }
        __stcs(dst + i, v);
    }
}

// ======================================================================
extern "C" void kernel_launch(void* const* d_in, const int* in_sizes, int n_in,
                              void* d_out, int out_size)
{
    const float* x      = (const float*)d_in[0];
    const float* corr   = (const float*)d_in[1];
    const float* map_w  = (const float*)d_in[2];
    const float* map_b  = (const float*)d_in[3];
    const float* mean_w = (const float*)d_in[4];
    const float* mean_b = (const float*)d_in[5];
    const float* cov_w  = (const float*)d_in[6];
    const float* cov_b  = (const float*)d_in[7];

    float* out = (float*)d_out;
    // outputs concatenated flat: corr1 (b,h,w,h,w), mean (b,h,w,2), det (b,h*w)
    float* out_corr1 = out;
    float* out_mean  = out + (size_t)NPIX * PLANE;
    float* out_det   = out_mean + (size_t)NPIX * 2;

    k_stats<<<NBLK1, 256>>>(x, map_w, map_b, mean_w, mean_b, cov_w, cov_b, out_mean);
    k_apply<<<NPIX, 192>>>(corr, out_corr1, out_mean, out_det);
}